// round 3
// baseline (speedup 1.0000x reference)
#include <cuda_runtime.h>
#include <cuda_bf16.h>
#include <math.h>

// Problem constants (fixed by the reference)
#define BB 4
#define SS 2048
#define DD 1024
#define HH 16
#define HD 64
#define MM (BB * SS)       // 8192 rows for projections

// ---------------------------------------------------------------------------
// Scratch: Q,K,V in [B,H,S,HD] layout. __device__ globals (no allocation).
// ---------------------------------------------------------------------------
__device__ float g_Q[BB * HH * SS * HD];
__device__ float g_K[BB * HH * SS * HD];
__device__ float g_V[BB * HH * SS * HD];

// ---------------------------------------------------------------------------
// Projection GEMM: Out[b,h,s,hd] = sum_k X[m,k] * W[n,k]
//   X: [8192,1024] row-major, W: [1024,1024] row-major ([out,in])
//   blockIdx.z selects which of Q/K/V projection this block computes.
// 128x128 tile, BK=16, 8x8/thread, 256 threads, register-prefetch pipeline.
// ---------------------------------------------------------------------------
#define PBM 128
#define PBN 128
#define PBK 16

__global__ __launch_bounds__(256) void proj_gemm_kernel(
    const float* __restrict__ Xq, const float* __restrict__ Xk,
    const float* __restrict__ Xv,
    const float* __restrict__ Wq, const float* __restrict__ Wk,
    const float* __restrict__ Wv,
    float* __restrict__ Oq, float* __restrict__ Ok, float* __restrict__ Ov)
{
    const float* X; const float* W; float* Out;
    if (blockIdx.z == 0)      { X = Xq; W = Wq; Out = Oq; }
    else if (blockIdx.z == 1) { X = Xk; W = Wk; Out = Ok; }
    else                      { X = Xv; W = Wv; Out = Ov; }

    __shared__ float As[PBK][PBM + 4];   // [k][m]
    __shared__ float Bs[PBK][PBN + 4];   // [k][n]

    const int bm = blockIdx.y * PBM;
    const int bn = blockIdx.x * PBN;
    const int tid = threadIdx.x;
    const int tx = tid & 15;
    const int ty = tid >> 4;

    // Each thread loads 2 A-float4 and 2 B-float4 per k-tile.
    int lrow[2], lkv[2];
#pragma unroll
    for (int r = 0; r < 2; r++) {
        int idx = tid + r * 256;
        lrow[r] = idx >> 2;
        lkv[r]  = (idx & 3) << 2;
    }

    float4 aReg[2], bReg[2];
#pragma unroll
    for (int r = 0; r < 2; r++) {
        aReg[r] = *(const float4*)&X[(size_t)(bm + lrow[r]) * DD + lkv[r]];
        bReg[r] = *(const float4*)&W[(size_t)(bn + lrow[r]) * DD + lkv[r]];
    }

    float acc[8][8];
#pragma unroll
    for (int i = 0; i < 8; i++)
#pragma unroll
        for (int j = 0; j < 8; j++) acc[i][j] = 0.0f;

    for (int k0 = 0; k0 < DD; k0 += PBK) {
        // Commit prefetched regs to smem.
#pragma unroll
        for (int r = 0; r < 2; r++) {
            As[lkv[r] + 0][lrow[r]] = aReg[r].x;
            As[lkv[r] + 1][lrow[r]] = aReg[r].y;
            As[lkv[r] + 2][lrow[r]] = aReg[r].z;
            As[lkv[r] + 3][lrow[r]] = aReg[r].w;
            Bs[lkv[r] + 0][lrow[r]] = bReg[r].x;
            Bs[lkv[r] + 1][lrow[r]] = bReg[r].y;
            Bs[lkv[r] + 2][lrow[r]] = bReg[r].z;
            Bs[lkv[r] + 3][lrow[r]] = bReg[r].w;
        }
        __syncthreads();

        // Prefetch next tile into registers (overlaps with compute below).
        if (k0 + PBK < DD) {
#pragma unroll
            for (int r = 0; r < 2; r++) {
                aReg[r] = *(const float4*)&X[(size_t)(bm + lrow[r]) * DD + k0 + PBK + lkv[r]];
                bReg[r] = *(const float4*)&W[(size_t)(bn + lrow[r]) * DD + k0 + PBK + lkv[r]];
            }
        }

#pragma unroll
        for (int kk = 0; kk < PBK; kk++) {
            float4 a0 = *(const float4*)&As[kk][ty * 8];
            float4 a1 = *(const float4*)&As[kk][ty * 8 + 4];
            float4 b0 = *(const float4*)&Bs[kk][tx * 8];
            float4 b1 = *(const float4*)&Bs[kk][tx * 8 + 4];
            float a[8] = {a0.x, a0.y, a0.z, a0.w, a1.x, a1.y, a1.z, a1.w};
            float b[8] = {b0.x, b0.y, b0.z, b0.w, b1.x, b1.y, b1.z, b1.w};
#pragma unroll
            for (int i = 0; i < 8; i++)
#pragma unroll
                for (int j = 0; j < 8; j++)
                    acc[i][j] = fmaf(a[i], b[j], acc[i][j]);
        }
        __syncthreads();
    }

    // Write in [B,H,S,HD] layout.
#pragma unroll
    for (int i = 0; i < 8; i++) {
        int m = bm + ty * 8 + i;
        int b = m >> 11;          // /2048
        int s = m & (SS - 1);
#pragma unroll
        for (int j = 0; j < 8; j += 4) {
            int n  = bn + tx * 8 + j;
            int h  = n >> 6;
            int hd = n & 63;
            float4 o = make_float4(acc[i][j], acc[i][j + 1], acc[i][j + 2], acc[i][j + 3]);
            *(float4*)&Out[(((size_t)(b * HH + h) * SS + s) * HD) + hd] = o;
        }
    }
}

// ---------------------------------------------------------------------------
// Flash attention (fp32, causal + pad mask), 64-query x 64-key tiles.
// grid: (S/64, H, B), 256 threads, 4x4 fragment/thread.
// Q,K transposed in smem (lane-contiguous-r loads -> conflict-free STS);
// P row-major (float4 stores, broadcast reads); V row-major (float4 both ways).
// ---------------------------------------------------------------------------
#define QT 64
#define KT 64
#define LDP 68

__global__ __launch_bounds__(256) void attn_kernel(
    const float* __restrict__ Q,    // [B,H,S,HD]
    const float* __restrict__ K,
    const float* __restrict__ V,
    const int*   __restrict__ pad_mask,  // [B,1,1,S]
    float* __restrict__ out)        // [B,S,D]
{
    extern __shared__ float sm[];
    float* Qt = sm;                 // [HD][LDP]  Qt[d][qr]
    float* Kt = Qt + HD * LDP;      // [HD][LDP]  Kt[d][kr]
    float* Vs = Kt + HD * LDP;      // [KT][LDP]  Vs[kr][hd]
    float* Ps = Vs + KT * LDP;      // [QT][LDP]  Ps[qr][kr]
    int* spad = (int*)(Ps + QT * LDP);  // [KT]

    const int bq = blockIdx.x;
    const int h  = blockIdx.y;
    const int b  = blockIdx.z;
    const int tid = threadIdx.x;
    const int tx = tid & 15;   // key / hd col group (4 each)
    const int ty = tid >> 4;   // query row group (4 each)

    const float* Qbh = Q + (size_t)(b * HH + h) * SS * HD;
    const float* Kbh = K + (size_t)(b * HH + h) * SS * HD;
    const float* Vbh = V + (size_t)(b * HH + h) * SS * HD;

    // Load Q tile transposed: Qt[d][qr]. r lane-contiguous => the 4 scalar
    // transposed STS per float4 hit 32 consecutive banks (conflict-free).
    for (int i = tid; i < QT * (HD / 4); i += 256) {
        int r = i & 63;               // query row in tile (lane-contiguous)
        int c = (i >> 6) << 2;        // d chunk
        float4 q = *(const float4*)&Qbh[(size_t)(bq * QT + r) * HD + c];
        Qt[(c + 0) * LDP + r] = q.x;
        Qt[(c + 1) * LDP + r] = q.y;
        Qt[(c + 2) * LDP + r] = q.z;
        Qt[(c + 3) * LDP + r] = q.w;
    }

    float acc[4][4];
#pragma unroll
    for (int i = 0; i < 4; i++)
#pragma unroll
        for (int j = 0; j < 4; j++) acc[i][j] = 0.0f;
    float mrow[4] = {-INFINITY, -INFINITY, -INFINITY, -INFINITY};
    float lrow[4] = {0.0f, 0.0f, 0.0f, 0.0f};

    const float scale = 0.03125f;   // 1/sqrt(1024)

    for (int kt = 0; kt <= bq; kt++) {
        __syncthreads();   // previous iteration's readers done

        // K transposed (lane-contiguous r, conflict-free STS); V row-major.
        for (int i = tid; i < KT * (HD / 4); i += 256) {
            int r = i & 63;
            int c = (i >> 6) << 2;
            float4 k4 = *(const float4*)&Kbh[(size_t)(kt * KT + r) * HD + c];
            Kt[(c + 0) * LDP + r] = k4.x;
            Kt[(c + 1) * LDP + r] = k4.y;
            Kt[(c + 2) * LDP + r] = k4.z;
            Kt[(c + 3) * LDP + r] = k4.w;
        }
        for (int i = tid; i < KT * (HD / 4); i += 256) {
            int r = i >> 4;
            int c = (i & 15) << 2;
            float4 v4 = *(const float4*)&Vbh[(size_t)(kt * KT + r) * HD + c];
            *(float4*)&Vs[r * LDP + c] = v4;
        }
        if (tid < KT) spad[tid] = pad_mask[(size_t)b * SS + kt * KT + tid];
        __syncthreads();

        // Scores: s[i][j] = Q[ty*4+i] . K[tx*4+j]   (Q broadcast, K cf-float4)
        float s[4][4];
#pragma unroll
        for (int i = 0; i < 4; i++)
#pragma unroll
            for (int j = 0; j < 4; j++) s[i][j] = 0.0f;
#pragma unroll 16
        for (int d = 0; d < HD; d++) {
            float4 qf = *(const float4*)&Qt[d * LDP + ty * 4];
            float4 kf = *(const float4*)&Kt[d * LDP + tx * 4];
            float qa[4] = {qf.x, qf.y, qf.z, qf.w};
            float ka[4] = {kf.x, kf.y, kf.z, kf.w};
#pragma unroll
            for (int i = 0; i < 4; i++)
#pragma unroll
                for (int j = 0; j < 4; j++)
                    s[i][j] = fmaf(qa[i], ka[j], s[i][j]);
        }

        // Scale + causal + pad masks (exact -10000 like the reference).
        int qg0 = bq * QT + ty * 4;
#pragma unroll
        for (int i = 0; i < 4; i++) {
#pragma unroll
            for (int j = 0; j < 4; j++) {
                int kloc = tx * 4 + j;
                int kg = kt * KT + kloc;
                bool valid = (kg <= qg0 + i) && (spad[kloc] != 0);
                s[i][j] = valid ? s[i][j] * scale : -10000.0f;
            }
        }

        // Online softmax; rows live across 16 consecutive lanes (same ty).
#pragma unroll
        for (int i = 0; i < 4; i++) {
            float tm = fmaxf(fmaxf(s[i][0], s[i][1]), fmaxf(s[i][2], s[i][3]));
#pragma unroll
            for (int off = 1; off < 16; off <<= 1)
                tm = fmaxf(tm, __shfl_xor_sync(0xffffffffu, tm, off));
            float nm = fmaxf(mrow[i], tm);
            float corr = __expf(mrow[i] - nm);
            float rs = 0.0f;
#pragma unroll
            for (int j = 0; j < 4; j++) {
                s[i][j] = __expf(s[i][j] - nm);
                rs += s[i][j];
            }
#pragma unroll
            for (int off = 1; off < 16; off <<= 1)
                rs += __shfl_xor_sync(0xffffffffu, rs, off);
            lrow[i] = lrow[i] * corr + rs;
            mrow[i] = nm;
#pragma unroll
            for (int j = 0; j < 4; j++) acc[i][j] *= corr;
            // Row-major P: conflict-free float4 store.
            *(float4*)&Ps[(ty * 4 + i) * LDP + tx * 4] =
                make_float4(s[i][0], s[i][1], s[i][2], s[i][3]);
        }
        __syncthreads();

        // O += P @ V : P read as broadcast float4 (per-row), V cf-float4.
#pragma unroll 4
        for (int kk = 0; kk < KT; kk += 4) {
            float4 p0 = *(const float4*)&Ps[(ty * 4 + 0) * LDP + kk];
            float4 p1 = *(const float4*)&Ps[(ty * 4 + 1) * LDP + kk];
            float4 p2 = *(const float4*)&Ps[(ty * 4 + 2) * LDP + kk];
            float4 p3 = *(const float4*)&Ps[(ty * 4 + 3) * LDP + kk];
            float pa[4][4] = {{p0.x, p0.y, p0.z, p0.w},
                              {p1.x, p1.y, p1.z, p1.w},
                              {p2.x, p2.y, p2.z, p2.w},
                              {p3.x, p3.y, p3.z, p3.w}};
#pragma unroll
            for (int u = 0; u < 4; u++) {
                float4 vf = *(const float4*)&Vs[(kk + u) * LDP + tx * 4];
                float va[4] = {vf.x, vf.y, vf.z, vf.w};
#pragma unroll
                for (int i = 0; i < 4; i++)
#pragma unroll
                    for (int j = 0; j < 4; j++)
                        acc[i][j] = fmaf(pa[i][u], va[j], acc[i][j]);
            }
        }
    }

    // Normalize and write output [B,S,D], col = h*HD + hd.
#pragma unroll
    for (int i = 0; i < 4; i++) {
        float inv = 1.0f / lrow[i];
        int qg = bq * QT + ty * 4 + i;
        float4 o = make_float4(acc[i][0] * inv, acc[i][1] * inv,
                               acc[i][2] * inv, acc[i][3] * inv);
        *(float4*)&out[((size_t)(b * SS + qg) * DD) + h * HD + tx * 4] = o;
    }
}

// ---------------------------------------------------------------------------
// Launch
// ---------------------------------------------------------------------------
extern "C" void kernel_launch(void* const* d_in, const int* in_sizes, int n_in,
                              void* d_out, int out_size)
{
    const float* q  = (const float*)d_in[0];
    const float* k  = (const float*)d_in[1];
    const float* v  = (const float*)d_in[2];
    const int*  pad = (const int*)d_in[3];
    // d_in[4] = attn_mask (causal tril) — applied analytically in-kernel
    const float* Wq = (const float*)d_in[5];
    const float* Wk = (const float*)d_in[6];
    const float* Wv = (const float*)d_in[7];
    float* out = (float*)d_out;

    float *gq, *gk, *gv;
    cudaGetSymbolAddress((void**)&gq, g_Q);
    cudaGetSymbolAddress((void**)&gk, g_K);
    cudaGetSymbolAddress((void**)&gv, g_V);

    dim3 pgrid(DD / PBN, MM / PBM, 3);   // (8, 64, 3) — Q,K,V in one launch
    proj_gemm_kernel<<<pgrid, 256>>>(q, k, v, Wq, Wk, Wv, gq, gk, gv);

    int smem_bytes = (4 * HD * LDP) * (int)sizeof(float) + KT * (int)sizeof(int);
    cudaFuncSetAttribute(attn_kernel, cudaFuncAttributeMaxDynamicSharedMemorySize,
                         smem_bytes);
    attn_kernel<<<dim3(SS / QT, HH, BB), 256, smem_bytes>>>(gq, gk, gv, pad, out);
}

// round 16
// speedup vs baseline: 2.3940x; 2.3940x over previous
#include <cuda_runtime.h>
#include <cuda_bf16.h>
#include <math.h>
#include <stdint.h>

// Problem constants
#define BB 4
#define SS 2048
#define DD 1024
#define HH 16
#define HD 64
#define MM (BB * SS)       // 8192

// ---------------------------------------------------------------------------
// Device scratch (no allocation).
// ---------------------------------------------------------------------------
__device__ __nv_bfloat16 g_Xhi[3ll * MM * DD];
__device__ __nv_bfloat16 g_Xlo[3ll * MM * DD];
__device__ __nv_bfloat16 g_Whi[3ll * DD * DD];
__device__ __nv_bfloat16 g_Wlo[3ll * DD * DD];
// Projected tensors, bf16 hi/lo. Q pre-scaled by 1/32. V stored transposed.
__device__ __nv_bfloat16 g_Qhi[(size_t)BB * HH * SS * HD];
__device__ __nv_bfloat16 g_Qlo[(size_t)BB * HH * SS * HD];
__device__ __nv_bfloat16 g_Khi[(size_t)BB * HH * SS * HD];
__device__ __nv_bfloat16 g_Klo[(size_t)BB * HH * SS * HD];
__device__ __nv_bfloat16 g_Vthi[(size_t)BB * HH * HD * SS];  // [B,H,HD,S]
__device__ __nv_bfloat16 g_Vtlo[(size_t)BB * HH * HD * SS];

// ---------------------------------------------------------------------------
// mma.sync m16n8k16 bf16 (sm_80+ baseline ISA)
// ---------------------------------------------------------------------------
__device__ __forceinline__ void mma16816(float* c, const uint32_t* a, const uint32_t* b) {
    asm volatile(
        "mma.sync.aligned.m16n8k16.row.col.f32.bf16.bf16.f32 "
        "{%0,%1,%2,%3}, {%4,%5,%6,%7}, {%8,%9}, {%0,%1,%2,%3};"
        : "+f"(c[0]), "+f"(c[1]), "+f"(c[2]), "+f"(c[3])
        : "r"(a[0]), "r"(a[1]), "r"(a[2]), "r"(a[3]), "r"(b[0]), "r"(b[1]));
}

// Split (x,y) into packed bf16x2 hi + lo words. Low 16 bits = x (low k index).
__device__ __forceinline__ void split2(float x, float y, uint32_t& hi, uint32_t& lo) {
    __nv_bfloat16 hx = __float2bfloat16(x);
    __nv_bfloat16 hy = __float2bfloat16(y);
    __nv_bfloat16 lx = __float2bfloat16(x - __bfloat162float(hx));
    __nv_bfloat16 ly = __float2bfloat16(y - __bfloat162float(hy));
    hi = (uint32_t)*(uint16_t*)&hx | ((uint32_t)*(uint16_t*)&hy << 16);
    lo = (uint32_t)*(uint16_t*)&lx | ((uint32_t)*(uint16_t*)&ly << 16);
}

// ---------------------------------------------------------------------------
// Split f32 -> bf16 hi/lo (vectorized by 4)
// ---------------------------------------------------------------------------
__global__ __launch_bounds__(256) void split_kernel(
    const float* __restrict__ src, __nv_bfloat16* __restrict__ hi,
    __nv_bfloat16* __restrict__ lo, int n4)
{
    int i = blockIdx.x * blockDim.x + threadIdx.x;
    if (i >= n4) return;
    float4 x = ((const float4*)src)[i];
    uint32_t h01, l01, h23, l23;
    split2(x.x, x.y, h01, l01);
    split2(x.z, x.w, h23, l23);
    ((uint32_t*)hi)[2 * i]     = h01;
    ((uint32_t*)hi)[2 * i + 1] = h23;
    ((uint32_t*)lo)[2 * i]     = l01;
    ((uint32_t*)lo)[2 * i + 1] = l23;
}

// ---------------------------------------------------------------------------
// HMMA projection GEMM (split-bf16, 3 terms): Out[m,n] = X[m,:] . W[n,:]
// Block 128x128, 8 warps (2x4), warp tile 64x32 = 4x4 m16n8k16 frags.
// Epilogue writes bf16 hi/lo: Q (scaled 1/32), K in [B,H,S,HD]; V in [B,H,HD,S].
// ---------------------------------------------------------------------------
#define SST 40                 // proj smem row stride in bf16 (rows hold 32)
#define TILE_HALF (128 * SST)

__global__ __launch_bounds__(256, 2) void proj_mma_kernel(
    const __nv_bfloat16* __restrict__ Xhi, const __nv_bfloat16* __restrict__ Xlo,
    const __nv_bfloat16* __restrict__ Whi, const __nv_bfloat16* __restrict__ Wlo,
    __nv_bfloat16* __restrict__ Qhi, __nv_bfloat16* __restrict__ Qlo,
    __nv_bfloat16* __restrict__ Khi, __nv_bfloat16* __restrict__ Klo,
    __nv_bfloat16* __restrict__ Vthi, __nv_bfloat16* __restrict__ Vtlo)
{
    __shared__ __nv_bfloat16 sAhi[TILE_HALF], sAlo[TILE_HALF];
    __shared__ __nv_bfloat16 sBhi[TILE_HALF], sBlo[TILE_HALF];

    const int tid = threadIdx.x;
    const int wid = tid >> 5;
    const int lid = tid & 31;
    const int wm  = (wid & 1) * 64;
    const int wn  = (wid >> 1) * 32;
    const int g   = lid >> 2;
    const int t2  = (lid & 3) * 2;

    const int bn = blockIdx.x * 128;
    const int bm = blockIdx.y * 128;
    const int z  = blockIdx.z;

    const __nv_bfloat16* Ahi = Xhi + (size_t)z * MM * DD;
    const __nv_bfloat16* Alo = Xlo + (size_t)z * MM * DD;
    const __nv_bfloat16* Bhi = Whi + (size_t)z * DD * DD;
    const __nv_bfloat16* Blo = Wlo + (size_t)z * DD * DD;

    float acc[4][4][4];
#pragma unroll
    for (int mt = 0; mt < 4; mt++)
#pragma unroll
        for (int nt = 0; nt < 4; nt++)
#pragma unroll
            for (int e = 0; e < 4; e++) acc[mt][nt][e] = 0.0f;

    const uint32_t* wAhi = (const uint32_t*)sAhi;
    const uint32_t* wAlo = (const uint32_t*)sAlo;
    const uint32_t* wBhi = (const uint32_t*)sBhi;
    const uint32_t* wBlo = (const uint32_t*)sBlo;

    for (int kc = 0; kc < DD; kc += 32) {
#pragma unroll
        for (int p = 0; p < 2; p++) {
            int idx = tid + p * 256;
            int r   = idx >> 2;
            int c16 = (idx & 3) * 8;
            int so  = r * SST + c16;
            size_t ga = (size_t)(bm + r) * DD + kc + c16;
            size_t gb = (size_t)(bn + r) * DD + kc + c16;
            *(uint4*)&sAhi[so] = *(const uint4*)&Ahi[ga];
            *(uint4*)&sAlo[so] = *(const uint4*)&Alo[ga];
            *(uint4*)&sBhi[so] = *(const uint4*)&Bhi[gb];
            *(uint4*)&sBlo[so] = *(const uint4*)&Blo[gb];
        }
        __syncthreads();

#pragma unroll
        for (int ko = 0; ko < 32; ko += 16) {
            const int cw = (ko + t2) >> 1;
            uint32_t ah[4][4], al[4][4], bh[4][2], bl[4][2];
#pragma unroll
            for (int mt = 0; mt < 4; mt++) {
                int r0 = (wm + mt * 16 + g) * (SST / 2);
                int r8 = r0 + 8 * (SST / 2);
                ah[mt][0] = wAhi[r0 + cw];
                ah[mt][1] = wAhi[r8 + cw];
                ah[mt][2] = wAhi[r0 + cw + 4];
                ah[mt][3] = wAhi[r8 + cw + 4];
            }
#pragma unroll
            for (int nt = 0; nt < 4; nt++) {
                int rn = (wn + nt * 8 + g) * (SST / 2);
                bh[nt][0] = wBhi[rn + cw];
                bh[nt][1] = wBhi[rn + cw + 4];
            }
#pragma unroll
            for (int mt = 0; mt < 4; mt++)
#pragma unroll
                for (int nt = 0; nt < 4; nt++)
                    mma16816(acc[mt][nt], ah[mt], bh[nt]);
#pragma unroll
            for (int nt = 0; nt < 4; nt++) {
                int rn = (wn + nt * 8 + g) * (SST / 2);
                bl[nt][0] = wBlo[rn + cw];
                bl[nt][1] = wBlo[rn + cw + 4];
            }
#pragma unroll
            for (int mt = 0; mt < 4; mt++)
#pragma unroll
                for (int nt = 0; nt < 4; nt++)
                    mma16816(acc[mt][nt], ah[mt], bl[nt]);
#pragma unroll
            for (int mt = 0; mt < 4; mt++) {
                int r0 = (wm + mt * 16 + g) * (SST / 2);
                int r8 = r0 + 8 * (SST / 2);
                al[mt][0] = wAlo[r0 + cw];
                al[mt][1] = wAlo[r8 + cw];
                al[mt][2] = wAlo[r0 + cw + 4];
                al[mt][3] = wAlo[r8 + cw + 4];
            }
#pragma unroll
            for (int mt = 0; mt < 4; mt++)
#pragma unroll
                for (int nt = 0; nt < 4; nt++)
                    mma16816(acc[mt][nt], al[mt], bh[nt]);
        }
        __syncthreads();
    }

    // Epilogue. Rows m0 (c0,c1) and m0+8 (c2,c3) are in the same 128-row block
    // => same batch; s1 = s0 + 8.
    if (z != 2) {
        __nv_bfloat16* Ohi = (z == 0) ? Qhi : Khi;
        __nv_bfloat16* Olo = (z == 0) ? Qlo : Klo;
        const float sc = (z == 0) ? 0.03125f : 1.0f;   // fold 1/sqrt(1024) into Q
#pragma unroll
        for (int mt = 0; mt < 4; mt++) {
#pragma unroll
            for (int nt = 0; nt < 4; nt++) {
                int n  = bn + wn + nt * 8 + t2;
                int h  = n >> 6;
                int hd = n & 63;
                int m0 = bm + wm + mt * 16 + g;
                int b0 = m0 >> 11, s0 = m0 & (SS - 1);
                size_t base = (((size_t)(b0 * HH + h) * SS + s0) * HD) + hd;
                uint32_t hi, lo;
                split2(acc[mt][nt][0] * sc, acc[mt][nt][1] * sc, hi, lo);
                *(uint32_t*)&Ohi[base] = hi;
                *(uint32_t*)&Olo[base] = lo;
                split2(acc[mt][nt][2] * sc, acc[mt][nt][3] * sc, hi, lo);
                *(uint32_t*)&Ohi[base + 8 * HD] = hi;
                *(uint32_t*)&Olo[base + 8 * HD] = lo;
            }
        }
    } else {
        // V transposed: Vt[b][h][hd][s]
#pragma unroll
        for (int mt = 0; mt < 4; mt++) {
#pragma unroll
            for (int nt = 0; nt < 4; nt++) {
                int n  = bn + wn + nt * 8 + t2;
                int h  = n >> 6;
                int hd = n & 63;
                int m0 = bm + wm + mt * 16 + g;
                int b0 = m0 >> 11, s0 = m0 & (SS - 1);
                size_t vb = ((size_t)(b0 * HH + h) * HD);
#pragma unroll
                for (int e = 0; e < 4; e++) {
                    int dd = hd + (e & 1);
                    int ss = s0 + ((e >> 1) * 8);
                    float v = acc[mt][nt][e];
                    __nv_bfloat16 hv = __float2bfloat16(v);
                    __nv_bfloat16 lv = __float2bfloat16(v - __bfloat162float(hv));
                    Vthi[(vb + dd) * SS + ss] = hv;
                    Vtlo[(vb + dd) * SS + ss] = lv;
                }
            }
        }
    }
}

// ---------------------------------------------------------------------------
// HMMA flash attention. Block = 128 threads (4 warps x 16 q-rows), 64-key
// tiles, causal + pad. QK^T and P.V both 3-term split-bf16. P stays in
// registers (C-frag of QK == A-frag of PV).
// ---------------------------------------------------------------------------
#define ASST 72   // attn smem row stride in bf16 (rows hold 64; 36 words -> cf)

__global__ __launch_bounds__(128, 3) void attn_mma_kernel(
    const __nv_bfloat16* __restrict__ Qhi, const __nv_bfloat16* __restrict__ Qlo,
    const __nv_bfloat16* __restrict__ Khi, const __nv_bfloat16* __restrict__ Klo,
    const __nv_bfloat16* __restrict__ Vthi, const __nv_bfloat16* __restrict__ Vtlo,
    const int* __restrict__ pad_mask, float* __restrict__ out)
{
    __shared__ __nv_bfloat16 sKhi[64 * ASST], sKlo[64 * ASST];
    __shared__ __nv_bfloat16 sVhi[64 * ASST], sVlo[64 * ASST];
    __shared__ int spad[64];

    const int bq = blockIdx.x;
    const int h  = blockIdx.y;
    const int b  = blockIdx.z;
    const int tid = threadIdx.x;
    const int w   = tid >> 5;
    const int lid = tid & 31;
    const int g   = lid >> 2;
    const int t   = lid & 3;
    const int t2  = t * 2;

    const size_t bh = (size_t)(b * HH + h);
    const __nv_bfloat16* Qh = Qhi + bh * SS * HD;
    const __nv_bfloat16* Ql = Qlo + bh * SS * HD;
    const __nv_bfloat16* Kh = Khi + bh * SS * HD;
    const __nv_bfloat16* Kl = Klo + bh * SS * HD;
    const __nv_bfloat16* Vh = Vthi + bh * HD * SS;
    const __nv_bfloat16* Vl = Vtlo + bh * HD * SS;

    const int qr0 = bq * 64 + w * 16 + g;    // global q row (c0,c1)
    const int qr1 = qr0 + 8;                 // global q row (c2,c3)

    // Q A-frags (held for the whole kernel): 4 d-steps, hi+lo.
    uint32_t qh[4][4], ql[4][4];
#pragma unroll
    for (int j = 0; j < 4; j++) {
        int c0 = j * 16 + t2;
        qh[j][0] = *(const uint32_t*)&Qh[(size_t)qr0 * HD + c0];
        qh[j][1] = *(const uint32_t*)&Qh[(size_t)qr1 * HD + c0];
        qh[j][2] = *(const uint32_t*)&Qh[(size_t)qr0 * HD + c0 + 8];
        qh[j][3] = *(const uint32_t*)&Qh[(size_t)qr1 * HD + c0 + 8];
        ql[j][0] = *(const uint32_t*)&Ql[(size_t)qr0 * HD + c0];
        ql[j][1] = *(const uint32_t*)&Ql[(size_t)qr1 * HD + c0];
        ql[j][2] = *(const uint32_t*)&Ql[(size_t)qr0 * HD + c0 + 8];
        ql[j][3] = *(const uint32_t*)&Ql[(size_t)qr1 * HD + c0 + 8];
    }

    float o[8][4];
#pragma unroll
    for (int nt = 0; nt < 8; nt++)
#pragma unroll
        for (int e = 0; e < 4; e++) o[nt][e] = 0.0f;
    float m0 = -INFINITY, m1 = -INFINITY, l0 = 0.0f, l1 = 0.0f;

    const uint32_t* wKh = (const uint32_t*)sKhi;
    const uint32_t* wKl = (const uint32_t*)sKlo;
    const uint32_t* wVh = (const uint32_t*)sVhi;
    const uint32_t* wVl = (const uint32_t*)sVlo;

    for (int kt = 0; kt <= bq; kt++) {
        __syncthreads();
        // Load K tile [64 keys][64 d] and V^T tile [64 d][64 keys], hi/lo.
#pragma unroll
        for (int p = 0; p < 4; p++) {
            int idx = tid + p * 128;           // 0..511
            int r   = idx >> 3;                // 0..63
            int c8  = (idx & 7) * 8;           // 0..56
            int so  = r * ASST + c8;
            size_t gk = (size_t)(kt * 64 + r) * HD + c8;
            *(uint4*)&sKhi[so] = *(const uint4*)&Kh[gk];
            *(uint4*)&sKlo[so] = *(const uint4*)&Kl[gk];
            size_t gv = (size_t)r * SS + kt * 64 + c8;
            *(uint4*)&sVhi[so] = *(const uint4*)&Vh[gv];
            *(uint4*)&sVlo[so] = *(const uint4*)&Vl[gv];
        }
        if (tid < 64) spad[tid] = pad_mask[(size_t)b * SS + kt * 64 + tid];
        __syncthreads();

        // Scores: s[nt] = Q-rows x K-keys(nt*8..nt*8+7), 3-term split.
        float s[8][4];
#pragma unroll
        for (int nt = 0; nt < 8; nt++)
#pragma unroll
            for (int e = 0; e < 4; e++) s[nt][e] = 0.0f;
#pragma unroll
        for (int j = 0; j < 4; j++) {
#pragma unroll
            for (int nt = 0; nt < 8; nt++) {
                int wb = (nt * 8 + g) * (ASST / 2) + j * 8 + t;
                uint32_t kb[2] = { wKh[wb], wKh[wb + 4] };
                uint32_t kbl[2] = { wKl[wb], wKl[wb + 4] };
                mma16816(s[nt], qh[j], kb);
                mma16816(s[nt], qh[j], kbl);
                mma16816(s[nt], ql[j], kb);
            }
        }

        // Masks: pad always; causal only on the diagonal tile.
        const bool diag = (kt == bq);
#pragma unroll
        for (int nt = 0; nt < 8; nt++) {
            int col0 = nt * 8 + t2;
            int p0 = spad[col0], p1 = spad[col0 + 1];
            int kg0 = kt * 64 + col0;
            if (!p0 || (diag && kg0     > qr0)) s[nt][0] = -10000.0f;
            if (!p1 || (diag && kg0 + 1 > qr0)) s[nt][1] = -10000.0f;
            if (!p0 || (diag && kg0     > qr1)) s[nt][2] = -10000.0f;
            if (!p1 || (diag && kg0 + 1 > qr1)) s[nt][3] = -10000.0f;
        }

        // Online softmax (rows live in lane quads: shuffle over offsets 1,2).
        float rm0 = -INFINITY, rm1 = -INFINITY;
#pragma unroll
        for (int nt = 0; nt < 8; nt++) {
            rm0 = fmaxf(rm0, fmaxf(s[nt][0], s[nt][1]));
            rm1 = fmaxf(rm1, fmaxf(s[nt][2], s[nt][3]));
        }
        rm0 = fmaxf(rm0, __shfl_xor_sync(0xffffffffu, rm0, 1));
        rm0 = fmaxf(rm0, __shfl_xor_sync(0xffffffffu, rm0, 2));
        rm1 = fmaxf(rm1, __shfl_xor_sync(0xffffffffu, rm1, 1));
        rm1 = fmaxf(rm1, __shfl_xor_sync(0xffffffffu, rm1, 2));
        float nm0 = fmaxf(m0, rm0), nm1 = fmaxf(m1, rm1);
        float c0 = __expf(m0 - nm0), c1 = __expf(m1 - nm1);
        m0 = nm0; m1 = nm1;
        float rs0 = 0.0f, rs1 = 0.0f;
#pragma unroll
        for (int nt = 0; nt < 8; nt++) {
            s[nt][0] = __expf(s[nt][0] - nm0);
            s[nt][1] = __expf(s[nt][1] - nm0);
            s[nt][2] = __expf(s[nt][2] - nm1);
            s[nt][3] = __expf(s[nt][3] - nm1);
            rs0 += s[nt][0] + s[nt][1];
            rs1 += s[nt][2] + s[nt][3];
            o[nt][0] *= c0; o[nt][1] *= c0;
            o[nt][2] *= c1; o[nt][3] *= c1;
        }
        rs0 += __shfl_xor_sync(0xffffffffu, rs0, 1);
        rs0 += __shfl_xor_sync(0xffffffffu, rs0, 2);
        rs1 += __shfl_xor_sync(0xffffffffu, rs1, 1);
        rs1 += __shfl_xor_sync(0xffffffffu, rs1, 2);
        l0 = l0 * c0 + rs0;
        l1 = l1 * c1 + rs1;

        // P.V: C-frags of s repack directly into A-frags (FA2 trick), 3 terms.
#pragma unroll
        for (int j = 0; j < 4; j++) {
            uint32_t ph[4], pl[4];
            split2(s[2 * j][0],     s[2 * j][1],     ph[0], pl[0]);
            split2(s[2 * j][2],     s[2 * j][3],     ph[1], pl[1]);
            split2(s[2 * j + 1][0], s[2 * j + 1][1], ph[2], pl[2]);
            split2(s[2 * j + 1][2], s[2 * j + 1][3], ph[3], pl[3]);
#pragma unroll
            for (int nt = 0; nt < 8; nt++) {
                int wb = (nt * 8 + g) * (ASST / 2) + j * 8 + t;
                uint32_t vb[2] = { wVh[wb], wVh[wb + 4] };
                uint32_t vbl[2] = { wVl[wb], wVl[wb + 4] };
                mma16816(o[nt], ph, vb);
                mma16816(o[nt], ph, vbl);
                mma16816(o[nt], pl, vb);
            }
        }
    }

    // Normalize and write out [B,S,D].
    float inv0 = 1.0f / l0, inv1 = 1.0f / l1;
#pragma unroll
    for (int nt = 0; nt < 8; nt++) {
        int d = nt * 8 + t2;
        float2 v0 = make_float2(o[nt][0] * inv0, o[nt][1] * inv0);
        *(float2*)&out[((size_t)(b * SS + qr0)) * DD + h * HD + d] = v0;
        float2 v1 = make_float2(o[nt][2] * inv1, o[nt][3] * inv1);
        *(float2*)&out[((size_t)(b * SS + qr1)) * DD + h * HD + d] = v1;
    }
}

// ---------------------------------------------------------------------------
// Launch
// ---------------------------------------------------------------------------
extern "C" void kernel_launch(void* const* d_in, const int* in_sizes, int n_in,
                              void* d_out, int out_size)
{
    const float* q  = (const float*)d_in[0];
    const float* k  = (const float*)d_in[1];
    const float* v  = (const float*)d_in[2];
    const int*  pad = (const int*)d_in[3];
    const float* Wq = (const float*)d_in[5];
    const float* Wk = (const float*)d_in[6];
    const float* Wv = (const float*)d_in[7];
    float* out = (float*)d_out;

    __nv_bfloat16 *xhi, *xlo, *whi, *wlo;
    __nv_bfloat16 *qhi, *qlo, *khi, *klo, *vthi, *vtlo;
    cudaGetSymbolAddress((void**)&xhi, g_Xhi);
    cudaGetSymbolAddress((void**)&xlo, g_Xlo);
    cudaGetSymbolAddress((void**)&whi, g_Whi);
    cudaGetSymbolAddress((void**)&wlo, g_Wlo);
    cudaGetSymbolAddress((void**)&qhi, g_Qhi);
    cudaGetSymbolAddress((void**)&qlo, g_Qlo);
    cudaGetSymbolAddress((void**)&khi, g_Khi);
    cudaGetSymbolAddress((void**)&klo, g_Klo);
    cudaGetSymbolAddress((void**)&vthi, g_Vthi);
    cudaGetSymbolAddress((void**)&vtlo, g_Vtlo);

    // Split inputs/weights into bf16 hi/lo.
    const int nx4 = MM * DD / 4;
    const int nw4 = DD * DD / 4;
    split_kernel<<<(nx4 + 255) / 256, 256>>>(q,  xhi + 0ll * MM * DD, xlo + 0ll * MM * DD, nx4);
    split_kernel<<<(nx4 + 255) / 256, 256>>>(k,  xhi + 1ll * MM * DD, xlo + 1ll * MM * DD, nx4);
    split_kernel<<<(nx4 + 255) / 256, 256>>>(v,  xhi + 2ll * MM * DD, xlo + 2ll * MM * DD, nx4);
    split_kernel<<<(nw4 + 255) / 256, 256>>>(Wq, whi + 0ll * DD * DD, wlo + 0ll * DD * DD, nw4);
    split_kernel<<<(nw4 + 255) / 256, 256>>>(Wk, whi + 1ll * DD * DD, wlo + 1ll * DD * DD, nw4);
    split_kernel<<<(nw4 + 255) / 256, 256>>>(Wv, whi + 2ll * DD * DD, wlo + 2ll * DD * DD, nw4);

    // HMMA projections -> split-bf16 Q (scaled), K, V^T.
    proj_mma_kernel<<<dim3(DD / 128, MM / 128, 3), 256>>>(
        xhi, xlo, whi, wlo, qhi, qlo, khi, klo, vthi, vtlo);

    // HMMA flash attention.
    attn_mma_kernel<<<dim3(SS / 64, HH, BB), 128>>>(
        qhi, qlo, khi, klo, vthi, vtlo, pad, out);
}